// round 1
// baseline (speedup 1.0000x reference)
#include <cuda_runtime.h>

// Problem dims (fixed by the dataset)
#define B_DIM 32
#define T_DIM 512
#define K_DIM 1024
#define N_DIM 1024
#define M_DIM (B_DIM * T_DIM)   // 16384

// Scratch for pre-activation Y = X @ W^T + b  (64 MB, static device global:
// allocation-guard safe)
__device__ float g_Y[(size_t)M_DIM * N_DIM];

// ----------------------------------------------------------------------------
// SGEMM: Y[m][n] = sum_k X[m][k] * W[n][k] + bias[n]
// 128x128 tile, BK=16, 256 threads, 8x8 per thread (split 4+4 fragments)
// ----------------------------------------------------------------------------
#define BM 128
#define BN 128
#define BK 16

__global__ void __launch_bounds__(256, 2)
gemm_kernel(const float* __restrict__ A,      // [M_DIM, K_DIM]
            const float* __restrict__ W,      // [N_DIM, K_DIM]
            const float* __restrict__ bias)   // [N_DIM]
{
    __shared__ float As[BK][BM];
    __shared__ float Bs[BK][BN];

    const int bm = blockIdx.y * BM;
    const int bn = blockIdx.x * BN;
    const int tid = threadIdx.x;

    // global->smem load mapping: 256 threads, each loads 2 float4 from A and W
    const int lr = tid >> 2;            // 0..63 (row within tile, +64 for second)
    const int lc = (tid & 3) << 2;      // 0,4,8,12 (k offset)

    // compute mapping: 16x16 threads, each 8x8 (rows {ty*4..+3, 64+ty*4..+3})
    const int ty = tid >> 4;            // 0..15
    const int tx = tid & 15;            // 0..15

    const float* Ab = A + (size_t)bm * K_DIM;
    const float* Wb = W + (size_t)bn * K_DIM;

    float acc[8][8];
#pragma unroll
    for (int i = 0; i < 8; i++)
#pragma unroll
        for (int j = 0; j < 8; j++) acc[i][j] = 0.0f;

    for (int k0 = 0; k0 < K_DIM; k0 += BK) {
        float4 a0 = *(const float4*)(Ab + (size_t)lr        * K_DIM + k0 + lc);
        float4 a1 = *(const float4*)(Ab + (size_t)(lr + 64) * K_DIM + k0 + lc);
        float4 w0 = *(const float4*)(Wb + (size_t)lr        * K_DIM + k0 + lc);
        float4 w1 = *(const float4*)(Wb + (size_t)(lr + 64) * K_DIM + k0 + lc);

        __syncthreads();   // protect smem from previous iteration's readers

        As[lc + 0][lr]      = a0.x; As[lc + 1][lr]      = a0.y;
        As[lc + 2][lr]      = a0.z; As[lc + 3][lr]      = a0.w;
        As[lc + 0][lr + 64] = a1.x; As[lc + 1][lr + 64] = a1.y;
        As[lc + 2][lr + 64] = a1.z; As[lc + 3][lr + 64] = a1.w;

        Bs[lc + 0][lr]      = w0.x; Bs[lc + 1][lr]      = w0.y;
        Bs[lc + 2][lr]      = w0.z; Bs[lc + 3][lr]      = w0.w;
        Bs[lc + 0][lr + 64] = w1.x; Bs[lc + 1][lr + 64] = w1.y;
        Bs[lc + 2][lr + 64] = w1.z; Bs[lc + 3][lr + 64] = w1.w;

        __syncthreads();

#pragma unroll
        for (int kk = 0; kk < BK; kk++) {
            float4 av0 = *(const float4*)&As[kk][ty * 4];
            float4 av1 = *(const float4*)&As[kk][64 + ty * 4];
            float4 bv0 = *(const float4*)&Bs[kk][tx * 4];
            float4 bv1 = *(const float4*)&Bs[kk][64 + tx * 4];

            float af[8] = {av0.x, av0.y, av0.z, av0.w, av1.x, av1.y, av1.z, av1.w};
            float bf[8] = {bv0.x, bv0.y, bv0.z, bv0.w, bv1.x, bv1.y, bv1.z, bv1.w};

#pragma unroll
            for (int i = 0; i < 8; i++)
#pragma unroll
                for (int j = 0; j < 8; j++)
                    acc[i][j] = fmaf(af[i], bf[j], acc[i][j]);
        }
    }

    // epilogue: add bias, write Y (float4 stores, columns contiguous per group)
#pragma unroll
    for (int i = 0; i < 8; i++) {
        int r = bm + ((i < 4) ? (ty * 4 + i) : (64 + ty * 4 + (i - 4)));
#pragma unroll
        for (int jb = 0; jb < 2; jb++) {
            int c = bn + jb * 64 + tx * 4;
            float4 v;
            v.x = acc[i][jb * 4 + 0] + bias[c + 0];
            v.y = acc[i][jb * 4 + 1] + bias[c + 1];
            v.z = acc[i][jb * 4 + 2] + bias[c + 2];
            v.w = acc[i][jb * 4 + 3] + bias[c + 3];
            *(float4*)(g_Y + (size_t)r * N_DIM + c) = v;
        }
    }
}

// ----------------------------------------------------------------------------
// Membrane scan: per (b, n) chain over t.
// v = f*v + (1-f)*y ; spike = (v >= 1) ; reset v=0 on spike.
// One thread per 4 consecutive n (float4). 8192 threads total.
// ----------------------------------------------------------------------------
__global__ void __launch_bounds__(128)
scan_kernel(float* __restrict__ out)   // out: [T, B, N]
{
    const int idx = blockIdx.x * blockDim.x + threadIdx.x;   // 0..8191
    const int b  = idx >> 8;            // 256 float4-groups per batch row
    const int n4 = (idx & 255) << 2;

    const float4* yp = (const float4*)(g_Y + ((size_t)b * T_DIM) * N_DIM + n4);
    float4*       op = (float4*)(out + (size_t)b * N_DIM + n4);

    const float f   = (float)exp(-0.01);   // matches jnp.exp(float32(-0.01))
    const float omf = 1.0f - f;

    float4 v = make_float4(0.f, 0.f, 0.f, 0.f);

#pragma unroll 4
    for (int t = 0; t < T_DIM; t++) {
        float4 y = yp[(size_t)t * (N_DIM / 4)];

        v.x = f * v.x + omf * y.x;
        v.y = f * v.y + omf * y.y;
        v.z = f * v.z + omf * y.z;
        v.w = f * v.w + omf * y.w;

        float4 s;
        s.x = (v.x >= 1.0f) ? 1.0f : 0.0f;
        s.y = (v.y >= 1.0f) ? 1.0f : 0.0f;
        s.z = (v.z >= 1.0f) ? 1.0f : 0.0f;
        s.w = (v.w >= 1.0f) ? 1.0f : 0.0f;

        // multiplicative reset (detach): v = (1-s)*v
        v.x = (s.x != 0.0f) ? 0.0f : v.x;
        v.y = (s.y != 0.0f) ? 0.0f : v.y;
        v.z = (s.z != 0.0f) ? 0.0f : v.z;
        v.w = (s.w != 0.0f) ? 0.0f : v.w;

        op[(size_t)t * ((size_t)B_DIM * N_DIM / 4)] = s;
    }
}

// ----------------------------------------------------------------------------
extern "C" void kernel_launch(void* const* d_in, const int* in_sizes, int n_in,
                              void* d_out, int out_size)
{
    const float* x    = (const float*)d_in[0];   // [B, T, 1024]
    const float* W    = (const float*)d_in[1];   // [1024, 1024]
    const float* bias = (const float*)d_in[2];   // [1024]
    float* out        = (float*)d_out;           // [T, B, 1024]

    dim3 grid(N_DIM / BN, M_DIM / BM);           // 8 x 128 = 1024 blocks
    gemm_kernel<<<grid, 256>>>(x, W, bias);

    // 8192 threads: 64 blocks x 128
    scan_kernel<<<(B_DIM * N_DIM / 4) / 128, 128>>>(out);
}